// round 15
// baseline (speedup 1.0000x reference)
#include <cuda_runtime.h>
#include <math.h>
#include <stdint.h>

#define BATCH   16
#define NHEADS  32
#define G       8      // kv heads
#define RQ      4      // query heads per kv head
#define D       128
#define BLK     256    // cache block size (fixed by layout)
#define MAXB    16     // cache blocks per sequence
#define CS      64     // positions per chunk CTA
#define MAXC    64     // max chunks per sequence (4096/64)
#define TS      32     // positions per tile
#define PSTR4   (G * (D / 4))   // float4 stride between positions = 256
#define NEG_INF (-1e30f)
#define QK_SCALE 0.08838834764831845f  // 1/sqrt(128)

// split-KV partial results: [B, G, chunk, rq]
__device__ float g_pm  [BATCH * G * MAXC * RQ];
__device__ float g_pl  [BATCH * G * MAXC * RQ];
__device__ float g_pacc[BATCH * G * MAXC * RQ * D];

__device__ __forceinline__ void cp16(uint32_t dst, const void* src) {
    asm volatile("cp.async.cg.shared.global [%0], [%1], 16;" :: "r"(dst), "l"(src));
}
__device__ __forceinline__ void cp_commit() {
    asm volatile("cp.async.commit_group;");
}
template <int N>
__device__ __forceinline__ void cp_wait() {
    asm volatile("cp.async.wait_group %0;" :: "n"(N));
}

// smem layout (float4 units) — SINGLE buffer, 35.3KB -> 6 CTAs/SM:
//   [0,    1024)  K buf (32 rows x 32 f4, row-XOR swizzled)  16KB
//   [1024, 2048)  V buf                                       16KB
//   [2048, 2176)  q   [chunk][head] float4, pre-scaled
//   [2176, 2208)  pt  [pos] float4 = 4 heads' exp weights
//   [2208, 2209)  red scratch (al[4])
#define KB_F4    0
#define VB_F4    1024
#define QSM_F4   2048
#define PT_F4    2176
#define RED_F4   2208
#define SMEM_F4  2209
#define SMEM_BYTES (SMEM_F4 * 16)   // 35344 B

__global__ __launch_bounds__(128, 6)
void attn_chunk_kernel(const float* __restrict__ q,
                       const float* __restrict__ knew,
                       const float* __restrict__ vnew,
                       const float* __restrict__ kcache,
                       const float* __restrict__ vcache,
                       const int*   __restrict__ ctx_lens,
                       const int*   __restrict__ btab,
                       const int*   __restrict__ slot_map)
{
    const int c = blockIdx.x;   // chunk (CS positions)
    const int g = blockIdx.y;   // kv head
    const int b = blockIdx.z;   // sequence

    const int ctx   = __ldg(&ctx_lens[b]);
    const int start = c * CS;
    if (start >= ctx) return;
    const int npos = min(CS, ctx - start);

    extern __shared__ float4 sm4[];
    float4* kbuf = sm4 + KB_F4;
    float4* vbuf = sm4 + VB_F4;
    float4* qsm  = sm4 + QSM_F4;
    float4* pt   = sm4 + PT_F4;
    float*  red  = (float*)(sm4 + RED_F4);

    const int tid  = threadIdx.x;
    const int lane = tid & 31;
    const int warp = tid >> 5;

    // chunk c sits inside cache block start/BLK at row offset start%BLK
    const int blkid = btab[b * MAXB + (start >> 8)];
    const size_t rowbase = (size_t)blkid * BLK + (start & (BLK - 1));
    const float4* kbase = (const float4*)kcache + rowbase * PSTR4 + g * (D / 4);
    const float4* vbase = (const float4*)vcache + rowbase * PSTR4 + g * (D / 4);

    const int lastLocal = (slot_map[b] >= 0) ? (ctx - 1 - start) : -1000000;
    const float4* knp = (const float4*)knew + (size_t)(b * G + g) * (D / 4);
    const float4* vnp = (const float4*)vnew + (size_t)(b * G + g) * (D / 4);

    const uint32_t kb_a = (uint32_t)__cvta_generic_to_shared(kbuf);
    const uint32_t vb_a = (uint32_t)__cvta_generic_to_shared(vbuf);

    const int ntiles = (npos + TS - 1) / TS;   // 1 or 2

    // ---- issue tile 0: K group then V group (separate commits) ----
    {
        const int rows = min(TS, npos);
        #pragma unroll
        for (int j = 0; j < 8; ++j) {
            int idx = tid + 128 * j;
            int row = idx >> 5, cc = idx & 31;
            if (row < rows) {
                uint32_t off = (uint32_t)((row * 32 + (cc ^ row)) * 16);
                cp16(kb_a + off, kbase + (size_t)row * PSTR4 + cc);
            }
        }
        cp_commit();   // group: K(0)
        #pragma unroll
        for (int j = 0; j < 8; ++j) {
            int idx = tid + 128 * j;
            int row = idx >> 5, cc = idx & 31;
            if (row < rows) {
                uint32_t off = (uint32_t)((row * 32 + (cc ^ row)) * 16);
                cp16(vb_a + off, vbase + (size_t)row * PSTR4 + cc);
            }
        }
        cp_commit();   // group: V(0)
    }

    // q into smem, pre-scaled, layout [chunk][head]
    {
        const float4* qb = (const float4*)q + (size_t)(b * NHEADS + g * RQ) * (D / 4);
        int cc = tid >> 2, h = tid & 3;
        float4 t4 = qb[h * 32 + cc];
        t4.x *= QK_SCALE; t4.y *= QK_SCALE; t4.z *= QK_SCALE; t4.w *= QK_SCALE;
        qsm[cc * 4 + h] = t4;
    }

    float4 acc0 = make_float4(0.f, 0.f, 0.f, 0.f);
    float4 acc1 = acc0, acc2 = acc0, acc3 = acc0;
    float m_run = NEG_INF, l_run = 0.f;   // per-warp (= per-head) running state

    for (int t = 0; t < ntiles; ++t) {
        const int t0 = t * TS;
        const int pvn = min(TS, npos - t0);
        const int fr = lastLocal - t0;
        const bool fresh = (fr >= 0 && fr < TS);

        cp_wait<1>();       // K(t) done; V(t) may still be in flight
        __syncthreads();    // (B) K tile + q visible CTA-wide

        // fresh-token K substitution (rare; uniform branch)
        if (fresh) {
            if (tid < 32) kbuf[fr * 32 + (tid ^ fr)] = knp[tid];
            __syncthreads();
        }

        // ---- score: warp = head, lane = position; 4 accumulators (ILP) ----
        // (V(t)'s 16KB load overlaps this phase)
        float s = NEG_INF;
        {
            const float4* krow = kbuf + lane * 32;
            float a0 = 0.f, a1 = 0.f, a2 = 0.f, a3 = 0.f;
            #pragma unroll
            for (int cc = 0; cc < 32; cc += 4) {
                float4 k0 = krow[(cc + 0) ^ lane];
                float4 q0 = qsm[(cc + 0) * 4 + warp];
                a0 += k0.x * q0.x + k0.y * q0.y + k0.z * q0.z + k0.w * q0.w;
                float4 k1 = krow[(cc + 1) ^ lane];
                float4 q1 = qsm[(cc + 1) * 4 + warp];
                a1 += k1.x * q1.x + k1.y * q1.y + k1.z * q1.z + k1.w * q1.w;
                float4 k2 = krow[(cc + 2) ^ lane];
                float4 q2 = qsm[(cc + 2) * 4 + warp];
                a2 += k2.x * q2.x + k2.y * q2.y + k2.z * q2.z + k2.w * q2.w;
                float4 k3 = krow[(cc + 3) ^ lane];
                float4 q3 = qsm[(cc + 3) * 4 + warp];
                a3 += k3.x * q3.x + k3.y * q3.y + k3.z * q3.z + k3.w * q3.w;
            }
            if (lane < pvn) s = (a0 + a1) + (a2 + a3);
        }

        // warp-local tile max
        float mt = s;
        #pragma unroll
        for (int off = 16; off > 0; off >>= 1)
            mt = fmaxf(mt, __shfl_xor_sync(0xffffffffu, mt, off));

        const float mn = fmaxf(m_run, mt);
        const float al = __expf(m_run - mn);
        m_run = mn;

        const float e = __expf(s - mn);                  // 0 for invalid lanes
        ((float*)pt)[lane * 4 + warp] = e;

        float lt = e;
        #pragma unroll
        for (int off = 16; off > 0; off >>= 1)
            lt += __shfl_xor_sync(0xffffffffu, lt, off);
        l_run = l_run * al + lt;

        if (lane == 0) red[warp] = al;

        cp_wait<0>();       // V(t) done
        __syncthreads();    // (C) pt + al + V tile visible

        // fresh-token V substitution (rare)
        if (fresh) {
            if (tid < 32) vbuf[fr * 32 + (tid ^ fr)] = vnp[tid];
            __syncthreads();
        }

        // ---- PV: warp w owns positions w, w+4, ... ----
        {
            const float al0 = red[0], al1 = red[1], al2 = red[2], al3 = red[3];
            acc0.x *= al0; acc0.y *= al0; acc0.z *= al0; acc0.w *= al0;
            acc1.x *= al1; acc1.y *= al1; acc1.z *= al1; acc1.w *= al1;
            acc2.x *= al2; acc2.y *= al2; acc2.z *= al2; acc2.w *= al2;
            acc3.x *= al3; acc3.y *= al3; acc3.z *= al3; acc3.w *= al3;

            #pragma unroll 8
            for (int p = warp; p < pvn; p += 4) {
                float4 v4 = vbuf[p * 32 + (lane ^ p)];
                float4 p4 = pt[p];
                acc0.x += p4.x * v4.x; acc0.y += p4.x * v4.y;
                acc0.z += p4.x * v4.z; acc0.w += p4.x * v4.w;
                acc1.x += p4.y * v4.x; acc1.y += p4.y * v4.y;
                acc1.z += p4.y * v4.z; acc1.w += p4.y * v4.w;
                acc2.x += p4.z * v4.x; acc2.y += p4.z * v4.y;
                acc2.z += p4.z * v4.z; acc2.w += p4.z * v4.w;
                acc3.x += p4.w * v4.x; acc3.y += p4.w * v4.y;
                acc3.z += p4.w * v4.z; acc3.w += p4.w * v4.w;
            }
        }

        // issue tile t+1 (K group, then V group) after all reads complete
        if (t + 1 < ntiles) {
            __syncthreads();    // (D)
            const int t1 = t0 + TS;
            const int rows = min(TS, npos - t1);
            #pragma unroll
            for (int j = 0; j < 8; ++j) {
                int idx = tid + 128 * j;
                int row = idx >> 5, cc = idx & 31;
                if (row < rows) {
                    uint32_t off = (uint32_t)((row * 32 + (cc ^ row)) * 16);
                    cp16(kb_a + off, kbase + (size_t)(t1 + row) * PSTR4 + cc);
                }
            }
            cp_commit();   // group: K(t+1)
            #pragma unroll
            for (int j = 0; j < 8; ++j) {
                int idx = tid + 128 * j;
                int row = idx >> 5, cc = idx & 31;
                if (row < rows) {
                    uint32_t off = (uint32_t)((row * 32 + (cc ^ row)) * 16);
                    cp16(vb_a + off, vbase + (size_t)(t1 + row) * PSTR4 + cc);
                }
            }
            cp_commit();   // group: V(t+1)
        }
    }

    // ---- epilogue: write split-KV partials ----
    const size_t pidx = ((size_t)(b * G + g) * MAXC + c) * RQ;
    if (lane == 0) {
        g_pm[pidx + warp] = m_run;
        g_pl[pidx + warp] = l_run;
    }

    __syncthreads();
    float4* ab = sm4;   // reuse K+V bufs: [warp][head][lane] float4 = 512 f4
    ab[(warp * 4 + 0) * 32 + lane] = acc0;
    ab[(warp * 4 + 1) * 32 + lane] = acc1;
    ab[(warp * 4 + 2) * 32 + lane] = acc2;
    ab[(warp * 4 + 3) * 32 + lane] = acc3;
    __syncthreads();

    const float* abf = (const float*)ab;
    #pragma unroll
    for (int e = tid; e < RQ * D; e += 128) {
        int h = e >> 7, d = e & 127;
        float A = abf[(0 * 4 + h) * 128 + d] + abf[(1 * 4 + h) * 128 + d]
                + abf[(2 * 4 + h) * 128 + d] + abf[(3 * 4 + h) * 128 + d];
        g_pacc[(pidx + h) * D + d] = A;
    }
}

// combine: one block per (b,g), 512 threads = 16 warps, PDL-launched.
// warp w: head hh = w&3, segment seg = w>>2 (16 chunks each) -> ONE 16-deep
// MLP batch of float4 loads, then a 4-way smem merge by warps 0-3.
__global__ __launch_bounds__(512)
void attn_combine_kernel(const int* __restrict__ ctx_lens,
                         float* __restrict__ out)
{
    // ---- pre-dependency work (overlaps chunk-kernel tail under PDL) ----
    const int bg = blockIdx.x;      // 0..127
    const int b  = bg >> 3;
    const int g  = bg & 7;
    const int nc = (__ldg(&ctx_lens[b]) + CS - 1) / CS;   // ctx_lens: harness input

    const int tid  = threadIdx.x;
    const int lane = tid & 31;      // float4 slice of D
    const int w    = tid >> 5;      // 0..15
    const int hh   = w & 3;
    const int seg  = w >> 2;        // 0..3

    const size_t base = ((size_t)bg * MAXC + seg * 16) * RQ + hh;

    // ---- dependency: chunk kernel's partials must be complete ----
    cudaGridDependencySynchronize();

    float mv[16], lv[16];
    float4 av[16];
    #pragma unroll
    for (int j = 0; j < 16; ++j) {
        const int cc = seg * 16 + j;
        if (cc < nc) {
            const size_t p = base + (size_t)j * RQ;
            mv[j] = g_pm[p];
            lv[j] = g_pl[p];
            av[j] = ((const float4*)&g_pacc[p * D])[lane];
        } else {
            mv[j] = NEG_INF; lv[j] = 0.f;
            av[j] = make_float4(0.f, 0.f, 0.f, 0.f);
        }
    }
    float M = mv[0];
    #pragma unroll
    for (int j = 1; j < 16; ++j) M = fmaxf(M, mv[j]);
    float L = 0.f;
    float4 A = make_float4(0.f, 0.f, 0.f, 0.f);
    #pragma unroll
    for (int j = 0; j < 16; ++j) {
        const float e = __expf(mv[j] - M);
        L   += e * lv[j];
        A.x += e * av[j].x; A.y += e * av[j].y;
        A.z += e * av[j].z; A.w += e * av[j].w;
    }

    __shared__ float  sM[16], sL[16];
    __shared__ float4 sA[16][32];
    sA[w][lane] = A;
    if (lane == 0) { sM[w] = M; sL[w] = L; }
    __syncthreads();

    if (w < 4) {   // warp w merges head w's 4 segments
        float Mt = sM[w];
        #pragma unroll
        for (int s2 = 1; s2 < 4; ++s2) Mt = fmaxf(Mt, sM[s2 * 4 + w]);
        float Lt = 0.f;
        float4 At = make_float4(0.f, 0.f, 0.f, 0.f);
        #pragma unroll
        for (int s2 = 0; s2 < 4; ++s2) {
            const int ww = s2 * 4 + w;
            const float e = __expf(sM[ww] - Mt);
            Lt += e * sL[ww];
            float4 a = sA[ww][lane];
            At.x += e * a.x; At.y += e * a.y;
            At.z += e * a.z; At.w += e * a.w;
        }
        const float inv = 1.0f / Lt;
        At.x *= inv; At.y *= inv; At.z *= inv; At.w *= inv;
        float4* op = (float4*)(out + ((size_t)b * NHEADS + g * RQ + w) * D);
        op[lane] = At;
    }
}

extern "C" void kernel_launch(void* const* d_in, const int* in_sizes, int n_in,
                              void* d_out, int out_size)
{
    const float* q    = (const float*)d_in[0];
    const float* k    = (const float*)d_in[1];
    const float* v    = (const float*)d_in[2];
    const float* kc   = (const float*)d_in[3];
    const float* vc   = (const float*)d_in[4];
    const int*   ctx  = (const int*)d_in[5];
    const int*   btab = (const int*)d_in[6];
    const int*   smap = (const int*)d_in[7];
    float* out = (float*)d_out;

    dim3 grid(MAXC, G, BATCH);   // 8192 CTAs, ~520 non-empty
    attn_chunk_kernel<<<grid, 128, SMEM_BYTES>>>(q, k, v, kc, vc, ctx, btab, smap);

    // PDL launch of combine: overlaps its launch/prelude with the chunk tail.
    cudaLaunchAttribute attrs[1];
    attrs[0].id = cudaLaunchAttributeProgrammaticStreamSerialization;
    attrs[0].val.programmaticStreamSerializationAllowed = 1;
    cudaLaunchConfig_t cfg = {};
    cfg.gridDim  = dim3(BATCH * G);
    cfg.blockDim = dim3(512);
    cfg.dynamicSmemBytes = 0;
    cfg.attrs    = attrs;
    cfg.numAttrs = 1;
    cudaError_t err = cudaLaunchKernelEx(&cfg, attn_combine_kernel, ctx, out);
    if (err != cudaSuccess) {
        // fallback: plain launch (still correct, just serialized)
        attn_combine_kernel<<<BATCH * G, 512>>>(ctx, out);
    }
}